// round 13
// baseline (speedup 1.0000x reference)
#include <cuda_runtime.h>
#include <cstdint>

#define NB 1024
#define NL 4096
#define NTB 512               // kernel B block
#define GRIDB 296             // 2 CTAs/SM exactly
#define NCHUNK 8
// 2*log2(e)/tau and ln(2)
#define K2F  3.3945765667975607f
#define LN2F 0.6931471805599453f
#define FIXSCALE 4294967296.0   // 2^32

__device__ int g_T[NB];
__device__ int g_off[NB * 4];              // label count before elem wwin*1024, per row
__device__ unsigned long long g_acc = 0;   // fixed-point sum, self-resetting
__device__ unsigned g_count = 0;           // ticket, wraps via atomicInc

__device__ __forceinline__ float ex2f(float x) {
    float r;
    asm("ex2.approx.f32 %0, %1;" : "=f"(r) : "f"(x));
    return r;
}

// ---------------- Kernel A: per-row label totals + coarse prefix (16 MB stream) ----
__global__ __launch_bounds__(256)
void count_kernel(const int* __restrict__ labels) {
    __shared__ int s_w[8];
    const int row  = blockIdx.x;
    const int t    = threadIdx.x;
    const int lane = t & 31;
    const int warp = t >> 5;               // 0..7, covers elems [warp*512, +512)

    const int4* lab4 = reinterpret_cast<const int4*>(labels + (size_t)row * NL);
    int4 a[4];
#pragma unroll
    for (int k = 0; k < 4; k++) a[k] = lab4[warp * 128 + k * 32 + lane];

    int s = 0;
#pragma unroll
    for (int k = 0; k < 4; k++) s += a[k].x + a[k].y + a[k].z + a[k].w;
#pragma unroll
    for (int d = 16; d; d >>= 1) s += __shfl_down_sync(0xffffffffu, s, d);
    if (lane == 0) s_w[warp] = s;
    __syncthreads();
    if (t == 0) {
        const int w0 = s_w[0], w1 = s_w[1], w2 = s_w[2], w3 = s_w[3];
        const int w4 = s_w[4], w5 = s_w[5], w6 = s_w[6], w7 = s_w[7];
        g_off[row * 4 + 0] = 0;
        g_off[row * 4 + 1] = w0 + w1;
        g_off[row * 4 + 2] = w0 + w1 + w2 + w3;
        g_off[row * 4 + 3] = w0 + w1 + w2 + w3 + w4 + w5;
        g_T[row]           = w0 + w1 + w2 + w3 + w4 + w5 + w6 + w7;
    }
}

// ---------------- Kernel B: decoupled math pass (no pre-math cross-warp wait) ------
__global__ __launch_bounds__(NTB, 2)
void math_kernel(const float* __restrict__ probs, const int* __restrict__ labels,
                 float* __restrict__ d_out) {
    __shared__ float s_S[NTB / 32], s_W[NTB / 32];

    const int t    = threadIdx.x;
    const int lane = t & 31;
    const int warp = t >> 5;        // 0..15
    const int wg   = warp >> 2;     // 0..3
    const int wwin = warp & 3;
    const int barid = 1 + wg;

    const int row = wg * GRIDB + blockIdx.x;   // transposed map: wg3 partially idle

    if (row < NB) {
        // uniform scalars from kernel A — no barrier, no ballot wall
        const int off = g_off[row * 4 + wwin];
        const int T   = g_T[row];

        const size_t roff  = (size_t)row * NL;
        const int    wbase = wwin * 1024;
        const int4*   lab4 = reinterpret_cast<const int4*>(labels + roff + wbase);
        const float4* pr4  = reinterpret_cast<const float4*>(probs  + roff + wbase);

        float4 pst[4];
#pragma unroll
        for (int k = 0; k < 4; k++) pst[k] = pr4[k * 32 + lane];

        const unsigned lt = (1u << lane) - 1u;
        float S0 = 0.0f, S1 = 0.0f, W0 = 0.0f, W1 = 0.0f;   // W in log2 units
        int running = off;
#pragma unroll
        for (int k = 0; k < NCHUNK; k++) {
            int4 a = lab4[k * 32 + lane];
            unsigned m0 = __ballot_sync(0xffffffffu, a.x);
            unsigned m1 = __ballot_sync(0xffffffffu, a.y);
            unsigned m2 = __ballot_sync(0xffffffffu, a.z);
            unsigned m3 = __ballot_sync(0xffffffffu, a.w);
            const int cfs = running + __popc(m0 & lt) + __popc(m1 & lt)
                                    + __popc(m2 & lt) + __popc(m3 & lt);
            running += __popc(m0) + __popc(m1) + __popc(m2) + __popc(m3);

            const float4 p = pst[k & 3];
            if (k + 4 < NCHUNK) pst[k & 3] = pr4[(k + 4) * 32 + lane];

            const int   kb = wbase + k * 128 + 4 * lane + 1 + T;   // idx+1+T
            const float r0 = __fdividef(1.0f, (float)kb);          // 1 RCP / 4 elems
            float kr[4];
            kr[0] = K2F * r0;                                      // folds 2*log2e/tau
#pragma unroll
            for (int j = 1; j < 4; j++) {
                const float tj = (float)j * r0;                    // Taylor 1/(kb+j)
                kr[j] = kr[0] * __fmaf_rn(tj, tj, 1.0f - tj);
            }
            float cf = (float)cfs;
            const int   v[4] = {a.x, a.y, a.z, a.w};
            const float q[4] = {p.x, p.y, p.z, p.w};
#pragma unroll
            for (int j = 0; j < 4; j++) {
                cf += v[j] ? 1.0f : 0.0f;
                const float f  = cf * kr[j];                       // 0 when c==0
                const float e  = ex2f(f);
                const float df = f - __log2f(q[j]);
                if (j & 1) { S1 += e; W1 = __fmaf_rn(e, df, W1); }
                else       { S0 += e; W0 = __fmaf_rn(e, df, W0); }
            }
        }
        float S = S0 + S1, W = W0 + W1;

        // warpgroup reduce (single barrier in the whole row path)
#pragma unroll
        for (int d = 16; d; d >>= 1) {
            S += __shfl_down_sync(0xffffffffu, S, d);
            W += __shfl_down_sync(0xffffffffu, W, d);
        }
        if (lane == 0) { s_S[warp] = S; s_W[warp] = W; }
        asm volatile("bar.sync %0, %1;" :: "r"(barid), "r"(128) : "memory");
        if (wwin == 0 && lane == 0) {
            const float St = s_S[wg*4+0] + s_S[wg*4+1] + s_S[wg*4+2] + s_S[wg*4+3];
            const float Wt = s_W[wg*4+0] + s_W[wg*4+1] + s_W[wg*4+2] + s_W[wg*4+3];
            const float rv = LN2F * (Wt / St) - __logf(St);        // ln2*(W/S) - ln(S)
            const long long q32 = __float2ll_rn((double)rv * FIXSCALE);
            atomicAdd(&g_acc, (unsigned long long)q32);            // integer: commutative
        }
    }

    // ticket: last CTA converts & resets
    __syncthreads();
    if (t == 0) {
        __threadfence();
        unsigned ticket = atomicInc(&g_count, GRIDB - 1);
        if (ticket == GRIDB - 1) {
            __threadfence();
            const long long v = (long long)g_acc;
            d_out[0] = (float)((double)v * (1.0 / FIXSCALE) / (double)NB);
            g_acc = 0;
        }
    }
}

extern "C" void kernel_launch(void* const* d_in, const int* in_sizes, int n_in,
                              void* d_out, int out_size) {
    const float* probs  = (const float*)d_in[0];   // output: (B, L, 1) f32
    const int*   labels = (const int*)d_in[1];     // labels: (B, L) i32
    count_kernel<<<NB, 256>>>(labels);
    math_kernel<<<GRIDB, NTB>>>(probs, labels, (float*)d_out);
}

// round 14
// speedup vs baseline: 1.1425x; 1.1425x over previous
#include <cuda_runtime.h>
#include <cstdint>

#define NB 1024
#define NL 4096
// 2*log2(e)/tau and ln(2)
#define K2F  3.3945765667975607f
#define LN2F 0.6931471805599453f
#define FIXSCALE 4294967296.0   // 2^32

__device__ int  g_T[NB];
__device__ int4 g_bits[NB * 32];           // chunk c: 4 ballot words (m0..m3) - 512 KB
__device__ int  g_offs[NB * 32];           // label count before chunk c       - 128 KB
__device__ unsigned long long g_acc = 0;   // fixed-point sum, self-resetting
__device__ unsigned g_count = 0;           // ticket, wraps via atomicInc

__device__ __forceinline__ float ex2f(float x) {
    float r;
    asm("ex2.approx.f32 %0, %1;" : "=f"(r) : "f"(x));
    return r;
}

// ---- Pass A: stream labels once; emit bit-packed labels + chunk offsets + T ----
// Chunk c covers elements [c*128, c*128+128). Word m_j bit l = label[c*128 + 4*l + j].
__global__ __launch_bounds__(256)
void pack_kernel(const int* __restrict__ labels) {
    __shared__ int s_w[8], s_base[8];
    const int row  = blockIdx.x;
    const int t    = threadIdx.x;
    const int lane = t & 31;
    const int warp = t >> 5;               // 0..7; owns chunks 4w..4w+3

    const int4* lab4 = reinterpret_cast<const int4*>(labels + (size_t)row * NL) + warp * 128;

    int cs[4];                             // chunk starts relative to warp (warp-uniform)
    int run = 0;
#pragma unroll
    for (int k = 0; k < 4; k++) {
        int4 a = lab4[k * 32 + lane];
        unsigned m0 = __ballot_sync(0xffffffffu, a.x);
        unsigned m1 = __ballot_sync(0xffffffffu, a.y);
        unsigned m2 = __ballot_sync(0xffffffffu, a.z);
        unsigned m3 = __ballot_sync(0xffffffffu, a.w);
        if (lane == 0)
            g_bits[row * 32 + warp * 4 + k] = make_int4((int)m0, (int)m1, (int)m2, (int)m3);
        cs[k] = run;
        run += __popc(m0) + __popc(m1) + __popc(m2) + __popc(m3);
    }
    if (lane == 0) s_w[warp] = run;
    __syncthreads();
    if (t == 0) {
        int base = 0;
#pragma unroll
        for (int w = 0; w < 8; w++) { s_base[w] = base; base += s_w[w]; }
        g_T[row] = base;
    }
    __syncthreads();
    if (lane < 4) {
        const int c = lane == 0 ? cs[0] : lane == 1 ? cs[1] : lane == 2 ? cs[2] : cs[3];
        g_offs[row * 32 + warp * 4 + lane] = s_base[warp] + c;
    }
}

// ---- Pass B: stream probs + packed bits; no label re-read, no pre-math cross-lane ----
__global__ __launch_bounds__(256)
void math_kernel(const float* __restrict__ probs, float* __restrict__ d_out) {
    __shared__ float s_S[8], s_W[8];

    const int row  = blockIdx.x;
    const int t    = threadIdx.x;
    const int lane = t & 31;
    const int warp = t >> 5;               // 0..7; owns chunks 4w..4w+3

    const int T = g_T[row];
    const float4* pr4 = reinterpret_cast<const float4*>(probs + (size_t)row * NL);

    // Front-batched loads: 4 coalesced float4 + 4 broadcast int4 + offsets.
    int4   bv[4];
    float4 pv[4];
    int    ofs[4];
#pragma unroll
    for (int k = 0; k < 4; k++) {
        const int c = warp * 4 + k;
        bv[k]  = g_bits[row * 32 + c];
        ofs[k] = g_offs[row * 32 + c];
        pv[k]  = pr4[c * 32 + lane];
    }

    const unsigned lt = (1u << lane) - 1u;
    float S0 = 0.0f, S1 = 0.0f, W0 = 0.0f, W1 = 0.0f;   // W in log2 units
#pragma unroll
    for (int k = 0; k < 4; k++) {
        const unsigned m[4] = {(unsigned)bv[k].x, (unsigned)bv[k].y,
                               (unsigned)bv[k].z, (unsigned)bv[k].w};
        // thread-local exclusive count at (chunk, lane, j=0)
        float cf = (float)(ofs[k] + __popc(m[0] & lt) + __popc(m[1] & lt)
                                  + __popc(m[2] & lt) + __popc(m[3] & lt));

        const int   kb = (warp * 4 + k) * 128 + 4 * lane + 1 + T;   // idx+1+T
        const float r0 = __fdividef(1.0f, (float)kb);               // 1 RCP / 4 elems
        float kr[4];
        kr[0] = K2F * r0;                                           // folds 2*log2e/tau
#pragma unroll
        for (int j = 1; j < 4; j++) {
            const float tj = (float)j * r0;                         // Taylor 1/(kb+j)
            kr[j] = kr[0] * __fmaf_rn(tj, tj, 1.0f - tj);
        }
        const float q[4] = {pv[k].x, pv[k].y, pv[k].z, pv[k].w};
#pragma unroll
        for (int j = 0; j < 4; j++) {
            cf += ((m[j] >> lane) & 1u) ? 1.0f : 0.0f;
            const float f  = cf * kr[j];                            // 0 when c==0
            const float e  = ex2f(f);
            const float df = f - __log2f(q[j]);
            if (j & 1) { S1 += e; W1 = __fmaf_rn(e, df, W1); }
            else       { S0 += e; W0 = __fmaf_rn(e, df, W0); }
        }
    }
    float S = S0 + S1, W = W0 + W1;

#pragma unroll
    for (int d = 16; d; d >>= 1) {
        S += __shfl_down_sync(0xffffffffu, S, d);
        W += __shfl_down_sync(0xffffffffu, W, d);
    }
    if (lane == 0) { s_S[warp] = S; s_W[warp] = W; }
    __syncthreads();
    if (t == 0) {
        float St = 0.0f, Wt = 0.0f;
#pragma unroll
        for (int w = 0; w < 8; w++) { St += s_S[w]; Wt += s_W[w]; }
        const float rv = LN2F * (Wt / St) - __logf(St);             // ln2*(W/S) - ln(S)
        const long long q32 = __float2ll_rn((double)rv * FIXSCALE);
        atomicAdd(&g_acc, (unsigned long long)q32);                 // integer: commutative
        __threadfence();
        unsigned ticket = atomicInc(&g_count, NB - 1);              // wraps after NB
        if (ticket == NB - 1) {
            __threadfence();
            const long long v = (long long)g_acc;
            d_out[0] = (float)((double)v * (1.0 / FIXSCALE) / (double)NB);
            g_acc = 0;                                              // reset for replay
        }
    }
}

extern "C" void kernel_launch(void* const* d_in, const int* in_sizes, int n_in,
                              void* d_out, int out_size) {
    const float* probs  = (const float*)d_in[0];   // output: (B, L, 1) f32
    const int*   labels = (const int*)d_in[1];     // labels: (B, L) i32
    pack_kernel<<<NB, 256>>>(labels);
    math_kernel<<<NB, 256>>>(probs, (float*)d_out);
}